// round 12
// baseline (speedup 1.0000x reference)
#include <cuda_runtime.h>
#include <cstdint>

#define T_TOK 8192
#define MDIM  1024
#define NEXP  8
#define DFFD  4096
#define CAP   1280

// ---------------- device scratch ----------------
__device__ __align__(256) float g_disp[(size_t)NEXP * CAP * MDIM];
__device__ __align__(256) float g_h   [(size_t)NEXP * CAP * DFFD];
__device__ __align__(256) float g_oute[(size_t)NEXP * CAP * MDIM];
__device__ __align__(256) float g_w1t [(size_t)NEXP * DFFD * MDIM];  // w1^T [E][n][k], tf32-rounded
__device__ __align__(256) float g_w2t [(size_t)NEXP * MDIM * DFFD];  // w2^T [E][n][k], tf32-rounded
__device__ int   g_expert[T_TOK];
__device__ float g_gate[T_TOK];
__device__ int   g_slot[T_TOK];

// ---------------- helpers ----------------
__device__ __forceinline__ uint32_t smem_u32(const void* p) {
    uint32_t a;
    asm("{ .reg .u64 t; cvta.to.shared.u64 t, %1; cvt.u32.u64 %0, t; }" : "=r"(a) : "l"(p));
    return a;
}
__device__ __forceinline__ float tf32r(float v) {
    uint32_t u;
    asm("cvt.rna.tf32.f32 %0, %1;" : "=r"(u) : "f"(v));
    return __uint_as_float(u);
}

#define CPASYNC16(dst, src) \
    asm volatile("cp.async.cg.shared.global [%0], [%1], 16;" :: "r"(dst), "l"(src) : "memory")
#define CPCOMMIT()  asm volatile("cp.async.commit_group;" ::: "memory")
#define CPWAIT(n)   asm volatile("cp.async.wait_group %0;" :: "n"(n) : "memory")

__device__ __forceinline__ void mma_tf32(float* d, const uint32_t* a, const uint32_t* b) {
    asm volatile(
        "mma.sync.aligned.m16n8k8.row.col.f32.tf32.tf32.f32 "
        "{%0,%1,%2,%3}, {%4,%5,%6,%7}, {%8,%9}, {%0,%1,%2,%3};"
        : "+f"(d[0]), "+f"(d[1]), "+f"(d[2]), "+f"(d[3])
        : "r"(a[0]), "r"(a[1]), "r"(a[2]), "r"(a[3]), "r"(b[0]), "r"(b[1]));
}

__device__ __forceinline__ void ldsm_x4(uint32_t* r, uint32_t addr) {
    asm volatile("ldmatrix.sync.aligned.m8n8.x4.shared.b16 {%0,%1,%2,%3}, [%4];"
        : "=r"(r[0]), "=r"(r[1]), "=r"(r[2]), "=r"(r[3]) : "r"(addr));
}

// ---------------- K1: gating ----------------
__global__ void gate_kernel(const float* __restrict__ x, const float* __restrict__ wg)
{
    int warp = (blockIdx.x * blockDim.x + threadIdx.x) >> 5;
    int lane = threadIdx.x & 31;
    if (warp >= T_TOK) return;

    const float* xr = x + (size_t)warp * MDIM;
    float acc[8] = {0.f,0.f,0.f,0.f,0.f,0.f,0.f,0.f};

    #pragma unroll 4
    for (int i = 0; i < MDIM / 32; i++) {
        int m = i * 32 + lane;
        float xv = __ldg(xr + m);
        const float4* w4 = reinterpret_cast<const float4*>(wg + (size_t)m * NEXP);
        float4 a = w4[0], b = w4[1];
        acc[0] += xv * a.x; acc[1] += xv * a.y;
        acc[2] += xv * a.z; acc[3] += xv * a.w;
        acc[4] += xv * b.x; acc[5] += xv * b.y;
        acc[6] += xv * b.z; acc[7] += xv * b.w;
    }
    #pragma unroll
    for (int e = 0; e < 8; e++)
        #pragma unroll
        for (int off = 16; off > 0; off >>= 1)
            acc[e] += __shfl_xor_sync(0xffffffffu, acc[e], off);

    if (lane == 0) {
        float mx = acc[0]; int bi = 0;
        #pragma unroll
        for (int e = 1; e < 8; e++)
            if (acc[e] > mx) { mx = acc[e]; bi = e; }
        float s = 0.f;
        #pragma unroll
        for (int e = 0; e < 8; e++) s += expf(acc[e] - mx);
        g_expert[warp] = bi;
        g_gate[warp]   = 1.0f / s;
    }
}

// ---------------- K2: ordered per-expert rank (two-level shuffle scan) ----------------
__global__ void pos_kernel()
{
    __shared__ int wtot[32][8];
    const int tid = threadIdx.x;
    const int lane = tid & 31, wp = tid >> 5;
    const int base_t = tid * 8;

    int cnt[8] = {0,0,0,0,0,0,0,0};
    int loc[8];
    #pragma unroll
    for (int i = 0; i < 8; i++) {
        int e = g_expert[base_t + i];
        loc[i] = e;
        cnt[e]++;
    }

    int inc[8];
    #pragma unroll
    for (int e = 0; e < 8; e++) inc[e] = cnt[e];
    #pragma unroll
    for (int off = 1; off < 32; off <<= 1) {
        #pragma unroll
        for (int e = 0; e < 8; e++) {
            int v = __shfl_up_sync(0xffffffffu, inc[e], off);
            if (lane >= off) inc[e] += v;
        }
    }
    if (lane == 31) {
        #pragma unroll
        for (int e = 0; e < 8; e++) wtot[wp][e] = inc[e];
    }
    __syncthreads();

    if (wp == 0) {
        int t[8];
        #pragma unroll
        for (int e = 0; e < 8; e++) t[e] = wtot[lane][e];
        #pragma unroll
        for (int off = 1; off < 32; off <<= 1) {
            #pragma unroll
            for (int e = 0; e < 8; e++) {
                int v = __shfl_up_sync(0xffffffffu, t[e], off);
                if (lane >= off) t[e] += v;
            }
        }
        #pragma unroll
        for (int e = 0; e < 8; e++) wtot[lane][e] = t[e];
    }
    __syncthreads();

    int run[8];
    #pragma unroll
    for (int e = 0; e < 8; e++)
        run[e] = (wp > 0 ? wtot[wp - 1][e] : 0) + inc[e] - cnt[e];

    #pragma unroll
    for (int i = 0; i < 8; i++) {
        int e = loc[i];
        int p = run[e]++;
        g_slot[base_t + i] = (p < CAP) ? (e * CAP + p) : -1;
    }
}

// ---------------- K3: scatter (+ tf32 rounding) ----------------
__global__ void scatter_kernel(const float* __restrict__ x)
{
    int t = blockIdx.x;
    int s = g_slot[t];
    if (s < 0) return;
    float4 v = reinterpret_cast<const float4*>(x + (size_t)t * MDIM)[threadIdx.x];
    v.x = tf32r(v.x); v.y = tf32r(v.y); v.z = tf32r(v.z); v.w = tf32r(v.w);
    reinterpret_cast<float4*>(g_disp + (size_t)s * MDIM)[threadIdx.x] = v;
}

// ---------------- K4: weight transpose (+ tf32 rounding) ----------------
// src [z][R][C] row-major -> dst [z][C][R]
__global__ void transpose_kernel(const float* __restrict__ src, float* __restrict__ dst,
                                 int R, int C)
{
    __shared__ float tile[32][33];
    int z = blockIdx.z;
    int c0 = blockIdx.x * 32, r0 = blockIdx.y * 32;
    const float* s = src + (size_t)z * R * C;
    float* d = dst + (size_t)z * R * C;
    int tx = threadIdx.x, ty = threadIdx.y;   // 32 x 8

    #pragma unroll
    for (int i = 0; i < 32; i += 8)
        tile[ty + i][tx] = s[(size_t)(r0 + ty + i) * C + c0 + tx];
    __syncthreads();
    #pragma unroll
    for (int i = 0; i < 32; i += 8)
        d[(size_t)(c0 + ty + i) * R + r0 + tx] = tf32r(tile[tx][ty + i]);
}

// ---------------- K5: tf32 mma.sync GEMM ----------------
// 256 threads, 8 warps (2x4), warp tile 64x32, CTA tile 128x128, BK=32.
// A [m][k] and B^T [n][k] both cached as [128][36] smem tiles (same banking),
// ALL fragments via ldmatrix.x4. 3-stage cp.async, one syncthreads/iter.
#define A_ST 4608   // 128*36 floats
#define B_ST 4608
#define GEMM_SMEM (3 * (A_ST + B_ST) * 4)   // 110592 bytes

template<bool RELU, bool CVT>
__global__ void __launch_bounds__(256, 2)
moe_gemm(const float* __restrict__ Ag, const float* __restrict__ Btg,
         const float* __restrict__ biasg, float* __restrict__ Cg,
         int Ndim, int Kdim)
{
    extern __shared__ float sm[];
    const uint32_t su = smem_u32(sm);
    const int tid = threadIdx.x;
    const int wid = tid >> 5, lane = tid & 31;
    const int g = lane >> 2, tg = lane & 3;
    const int wm = (wid >> 2) * 64;          // warp row base: 0 / 64
    const int wn = (wid & 3) * 32;           // warp col base: 0/32/64/96

    // ldmatrix per-lane source rows
    const int lrowA = (lane & 7) + ((lane >> 3) & 1) * 8;   // 0..15
    const int lcolA = (lane >> 4) * 4;                      // 0 or 4
    const int lrowB = wn + (lane >> 3) * 8 + (lane & 7);    // n row for B matrices

    const int z = blockIdx.z;
    const float* A  = Ag  + (size_t)z * CAP * Kdim + (size_t)(blockIdx.y * 128) * Kdim;
    const float* Bt = Btg + (size_t)z * Ndim * Kdim + (size_t)(blockIdx.x * 128) * Kdim;
    const float* bias = biasg + (size_t)z * Ndim + blockIdx.x * 128;
    float* C = Cg + (size_t)z * CAP * Ndim + (size_t)(blockIdx.y * 128) * Ndim + blockIdx.x * 128;

    const int row = tid >> 1, seg = (tid & 1) * 16;   // loaders: 2 thr/row, 16 floats each

    float acc[4][4][4];
    #pragma unroll
    for (int i = 0; i < 4; i++)
        #pragma unroll
        for (int j = 0; j < 4; j++)
            #pragma unroll
            for (int q = 0; q < 4; q++) acc[i][j][q] = 0.f;

    auto load_stage = [&](int kt, int s) {
        const float* ag = A + (size_t)row * Kdim + kt * 32 + seg;
        uint32_t ad = su + (uint32_t)(s * (A_ST + B_ST) + row * 36 + seg) * 4;
        #pragma unroll
        for (int i = 0; i < 4; i++)
            CPASYNC16(ad + i * 16, ag + i * 4);
        const float* bg = Bt + (size_t)row * Kdim + kt * 32 + seg;
        uint32_t bd = su + (uint32_t)(s * (A_ST + B_ST) + A_ST + row * 36 + seg) * 4;
        #pragma unroll
        for (int i = 0; i < 4; i++)
            CPASYNC16(bd + i * 16, bg + i * 4);
        CPCOMMIT();
    };

    const int KT = Kdim >> 5;   // 32 or 128
    load_stage(0, 0);
    load_stage(1, 1);

    int s = 0;          // stage holding kt
    int sw = 2;         // stage to write kt+2 into
    for (int kt = 0; kt < KT; kt++) {
        if (kt + 1 < KT) { CPWAIT(1); } else { CPWAIT(0); }
        __syncthreads();

        const uint32_t stg = su + (uint32_t)(s * (A_ST + B_ST)) * 4;
        const uint32_t abase = stg + (uint32_t)((wm + lrowA) * 36 + lcolA) * 4;
        const uint32_t bbase = stg + (uint32_t)(A_ST + lrowB * 36) * 4;

        #pragma unroll
        for (int ks = 0; ks < 4; ks++) {
            const int k0 = ks * 8;
            uint32_t afr[4][4], b0[4], b1[4];
            #pragma unroll
            for (int i = 0; i < 4; i++)
                ldsm_x4(afr[i], abase + (uint32_t)(i * 16 * 36 + k0) * 4);
            ldsm_x4(b0, bbase + (uint32_t)(k0) * 4);       // j=0..3, k half 0
            ldsm_x4(b1, bbase + (uint32_t)(k0 + 4) * 4);   // j=0..3, k half 1
            #pragma unroll
            for (int i = 0; i < 4; i++)
                #pragma unroll
                for (int j = 0; j < 4; j++) {
                    uint32_t bf[2] = { b0[j], b1[j] };
                    mma_tf32(acc[i][j], afr[i], bf);
                }
        }

        if (kt + 2 < KT) load_stage(kt + 2, sw);
        if (++s == 3) s = 0;
        if (++sw == 3) sw = 0;
    }

    // epilogue
    #pragma unroll
    for (int j = 0; j < 4; j++) {
        const int col = wn + j * 8 + 2 * tg;
        float2 bv = *reinterpret_cast<const float2*>(bias + col);
        #pragma unroll
        for (int i = 0; i < 4; i++) {
            const int r0 = wm + i * 16 + g;
            float v00 = acc[i][j][0] + bv.x, v01 = acc[i][j][1] + bv.y;
            float v10 = acc[i][j][2] + bv.x, v11 = acc[i][j][3] + bv.y;
            if (RELU) {
                v00 = fmaxf(v00, 0.f); v01 = fmaxf(v01, 0.f);
                v10 = fmaxf(v10, 0.f); v11 = fmaxf(v11, 0.f);
            }
            if (CVT) {
                v00 = tf32r(v00); v01 = tf32r(v01);
                v10 = tf32r(v10); v11 = tf32r(v11);
            }
            *reinterpret_cast<float2*>(C + (size_t)r0 * Ndim + col) = make_float2(v00, v01);
            *reinterpret_cast<float2*>(C + (size_t)(r0 + 8) * Ndim + col) = make_float2(v10, v11);
        }
    }
}

// ---------------- K6: gather ----------------
__global__ void gather_kernel(float* __restrict__ out)
{
    int t = blockIdx.x;
    int s = g_slot[t];
    float4* dst = reinterpret_cast<float4*>(out + (size_t)t * MDIM);
    if (s < 0) {
        dst[threadIdx.x] = make_float4(0.f, 0.f, 0.f, 0.f);
        return;
    }
    float g = g_gate[t];
    float4 v = reinterpret_cast<const float4*>(g_oute + (size_t)s * MDIM)[threadIdx.x];
    dst[threadIdx.x] = make_float4(v.x * g, v.y * g, v.z * g, v.w * g);
}

// ---------------- launch ----------------
extern "C" void kernel_launch(void* const* d_in, const int* in_sizes, int n_in,
                              void* d_out, int out_size)
{
    const float* x  = (const float*)d_in[0];
    const float* wg = (const float*)d_in[1];
    const float* w1 = (const float*)d_in[2];   // [E, M, DFF]
    const float* b1 = (const float*)d_in[3];
    const float* w2 = (const float*)d_in[4];   // [E, DFF, M]
    const float* b2 = (const float*)d_in[5];
    float* out = (float*)d_out;

    float *disp, *h, *oute, *w1t, *w2t;
    cudaGetSymbolAddress((void**)&disp, g_disp);
    cudaGetSymbolAddress((void**)&h,    g_h);
    cudaGetSymbolAddress((void**)&oute, g_oute);
    cudaGetSymbolAddress((void**)&w1t,  g_w1t);
    cudaGetSymbolAddress((void**)&w2t,  g_w2t);

    cudaFuncSetAttribute(moe_gemm<true, true>,
                         cudaFuncAttributeMaxDynamicSharedMemorySize, GEMM_SMEM);
    cudaFuncSetAttribute(moe_gemm<false, false>,
                         cudaFuncAttributeMaxDynamicSharedMemorySize, GEMM_SMEM);

    // weight transposes to [n][k] (+ tf32 rounding)
    {
        dim3 blk(32, 8);
        transpose_kernel<<<dim3(DFFD / 32, MDIM / 32, NEXP), blk>>>(w1, w1t, MDIM, DFFD);
        transpose_kernel<<<dim3(MDIM / 32, DFFD / 32, NEXP), blk>>>(w2, w2t, DFFD, MDIM);
    }

    gate_kernel<<<T_TOK / 8, 256>>>(x, wg);
    pos_kernel<<<1, 1024>>>();
    scatter_kernel<<<T_TOK, 256>>>(x);

    // GEMM1: h = relu(disp @ w1 + b1)
    moe_gemm<true, true><<<dim3(DFFD / 128, CAP / 128, NEXP), 256, GEMM_SMEM>>>(
        disp, w1t, b1, h, DFFD, MDIM);

    // GEMM2: oute = h @ w2 + b2
    moe_gemm<false, false><<<dim3(MDIM / 128, CAP / 128, NEXP), 256, GEMM_SMEM>>>(
        h, w2t, b2, oute, MDIM, DFFD);

    gather_kernel<<<T_TOK, 256>>>(out);
}

// round 13
// speedup vs baseline: 1.4249x; 1.4249x over previous
#include <cuda_runtime.h>
#include <cstdint>

#define T_TOK 8192
#define MDIM  1024
#define NEXP  8
#define DFFD  4096
#define CAP   1280

// ---------------- device scratch ----------------
__device__ __align__(256) float g_disp[(size_t)NEXP * CAP * MDIM];
__device__ __align__(256) float g_h   [(size_t)NEXP * CAP * DFFD];
__device__ __align__(256) float g_oute[(size_t)NEXP * CAP * MDIM];
__device__ int   g_expert[T_TOK];
__device__ float g_gate[T_TOK];
__device__ int   g_slot[T_TOK];

// ---------------- helpers ----------------
__device__ __forceinline__ uint32_t smem_u32(const void* p) {
    uint32_t a;
    asm("{ .reg .u64 t; cvta.to.shared.u64 t, %1; cvt.u32.u64 %0, t; }" : "=r"(a) : "l"(p));
    return a;
}
__device__ __forceinline__ float tf32r(float v) {
    uint32_t u;
    asm("cvt.rna.tf32.f32 %0, %1;" : "=r"(u) : "f"(v));
    return __uint_as_float(u);
}

#define CPASYNC16(dst, src) \
    asm volatile("cp.async.cg.shared.global [%0], [%1], 16;" :: "r"(dst), "l"(src) : "memory")
#define CPCOMMIT()  asm volatile("cp.async.commit_group;" ::: "memory")
#define CPWAIT(n)   asm volatile("cp.async.wait_group %0;" :: "n"(n) : "memory")

__device__ __forceinline__ void mma_tf32(float* d, const uint32_t* a, const uint32_t* b) {
    asm volatile(
        "mma.sync.aligned.m16n8k8.row.col.f32.tf32.tf32.f32 "
        "{%0,%1,%2,%3}, {%4,%5,%6,%7}, {%8,%9}, {%0,%1,%2,%3};"
        : "+f"(d[0]), "+f"(d[1]), "+f"(d[2]), "+f"(d[3])
        : "r"(a[0]), "r"(a[1]), "r"(a[2]), "r"(a[3]), "r"(b[0]), "r"(b[1]));
}

__device__ __forceinline__ void ldsm_x4(uint32_t* r, uint32_t addr) {
    asm volatile("ldmatrix.sync.aligned.m8n8.x4.shared.b16 {%0,%1,%2,%3}, [%4];"
        : "=r"(r[0]), "=r"(r[1]), "=r"(r[2]), "=r"(r[3]) : "r"(addr));
}

// ---------------- K1: gating ----------------
__global__ void gate_kernel(const float* __restrict__ x, const float* __restrict__ wg)
{
    int warp = (blockIdx.x * blockDim.x + threadIdx.x) >> 5;
    int lane = threadIdx.x & 31;
    if (warp >= T_TOK) return;

    const float* xr = x + (size_t)warp * MDIM;
    float acc[8] = {0.f,0.f,0.f,0.f,0.f,0.f,0.f,0.f};

    #pragma unroll 4
    for (int i = 0; i < MDIM / 32; i++) {
        int m = i * 32 + lane;
        float xv = __ldg(xr + m);
        const float4* w4 = reinterpret_cast<const float4*>(wg + (size_t)m * NEXP);
        float4 a = w4[0], b = w4[1];
        acc[0] += xv * a.x; acc[1] += xv * a.y;
        acc[2] += xv * a.z; acc[3] += xv * a.w;
        acc[4] += xv * b.x; acc[5] += xv * b.y;
        acc[6] += xv * b.z; acc[7] += xv * b.w;
    }
    #pragma unroll
    for (int e = 0; e < 8; e++)
        #pragma unroll
        for (int off = 16; off > 0; off >>= 1)
            acc[e] += __shfl_xor_sync(0xffffffffu, acc[e], off);

    if (lane == 0) {
        float mx = acc[0]; int bi = 0;
        #pragma unroll
        for (int e = 1; e < 8; e++)
            if (acc[e] > mx) { mx = acc[e]; bi = e; }
        float s = 0.f;
        #pragma unroll
        for (int e = 0; e < 8; e++) s += expf(acc[e] - mx);
        g_expert[warp] = bi;
        g_gate[warp]   = 1.0f / s;
    }
}

// ---------------- K2: ordered per-expert rank (two-level shuffle scan) ----------------
__global__ void pos_kernel()
{
    __shared__ int wtot[32][8];
    const int tid = threadIdx.x;
    const int lane = tid & 31, wp = tid >> 5;
    const int base_t = tid * 8;

    int cnt[8] = {0,0,0,0,0,0,0,0};
    int loc[8];
    #pragma unroll
    for (int i = 0; i < 8; i++) {
        int e = g_expert[base_t + i];
        loc[i] = e;
        cnt[e]++;
    }

    int inc[8];
    #pragma unroll
    for (int e = 0; e < 8; e++) inc[e] = cnt[e];
    #pragma unroll
    for (int off = 1; off < 32; off <<= 1) {
        #pragma unroll
        for (int e = 0; e < 8; e++) {
            int v = __shfl_up_sync(0xffffffffu, inc[e], off);
            if (lane >= off) inc[e] += v;
        }
    }
    if (lane == 31) {
        #pragma unroll
        for (int e = 0; e < 8; e++) wtot[wp][e] = inc[e];
    }
    __syncthreads();

    if (wp == 0) {
        int t[8];
        #pragma unroll
        for (int e = 0; e < 8; e++) t[e] = wtot[lane][e];
        #pragma unroll
        for (int off = 1; off < 32; off <<= 1) {
            #pragma unroll
            for (int e = 0; e < 8; e++) {
                int v = __shfl_up_sync(0xffffffffu, t[e], off);
                if (lane >= off) t[e] += v;
            }
        }
        #pragma unroll
        for (int e = 0; e < 8; e++) wtot[lane][e] = t[e];
    }
    __syncthreads();

    int run[8];
    #pragma unroll
    for (int e = 0; e < 8; e++)
        run[e] = (wp > 0 ? wtot[wp - 1][e] : 0) + inc[e] - cnt[e];

    #pragma unroll
    for (int i = 0; i < 8; i++) {
        int e = loc[i];
        int p = run[e]++;
        g_slot[base_t + i] = (p < CAP) ? (e * CAP + p) : -1;
    }
}

// ---------------- K3: scatter (+ tf32 rounding) ----------------
__global__ void scatter_kernel(const float* __restrict__ x)
{
    int t = blockIdx.x;
    int s = g_slot[t];
    if (s < 0) return;
    float4 v = reinterpret_cast<const float4*>(x + (size_t)t * MDIM)[threadIdx.x];
    v.x = tf32r(v.x); v.y = tf32r(v.y); v.z = tf32r(v.z); v.w = tf32r(v.w);
    reinterpret_cast<float4*>(g_disp + (size_t)s * MDIM)[threadIdx.x] = v;
}

// ---------------- K4: tf32 mma.sync GEMM ----------------
// 256 threads, 8 warps (2x4), warp tile 64x32, CTA tile 128x128, BK=32.
// 3-stage cp.async, one syncthreads/iter (load kt+2).
// A fragments via ldmatrix.x4; B fragments raw f32 (HW tf32 truncation).
// smem As [128][36], Bs [32][136] (both conflict-free).
#define A_ST 4608   // 128*36 floats per stage
#define B_ST 4352   // 32*136 floats per stage
#define NSTAGE 3
#define GEMM_SMEM (NSTAGE * (A_ST + B_ST) * 4)   // 107520 bytes

template<bool RELU, bool CVT>
__global__ void __launch_bounds__(256, 2)
moe_gemm(const float* __restrict__ Ag, const float* __restrict__ Bg,
         const float* __restrict__ biasg, float* __restrict__ Cg,
         int Ndim, int Kdim)
{
    extern __shared__ float sm[];
    const uint32_t su = smem_u32(sm);
    const int tid = threadIdx.x;
    const int wid = tid >> 5, lane = tid & 31;
    const int g = lane >> 2, tg = lane & 3;
    const int wm = (wid >> 2) * 64;          // warp row base: 0 / 64
    const int wn = (wid & 3) * 32;           // warp col base: 0/32/64/96

    // ldmatrix per-lane source row/col within the A tile
    const int lrow = (lane & 7) + ((lane >> 3) & 1) * 8;   // 0..15
    const int lcol = (lane >> 4) * 4;                      // 0 or 4

    const int z = blockIdx.z;
    const float* A = Ag + (size_t)z * CAP * Kdim + (size_t)(blockIdx.y * 128) * Kdim;
    const float* B = Bg + (size_t)z * Kdim * Ndim + blockIdx.x * 128;
    const float* bias = biasg + (size_t)z * Ndim + blockIdx.x * 128;
    float* C = Cg + (size_t)z * CAP * Ndim + (size_t)(blockIdx.y * 128) * Ndim + blockIdx.x * 128;

    const int arow = tid >> 1, acol = (tid & 1) * 16;  // A: 2 thr/row, 4x16B
    const int brow = tid >> 3, bseg = (tid & 7) * 4;   // B: 8 thr/row, 4x16B stride 128B

    float acc[4][4][4];
    #pragma unroll
    for (int i = 0; i < 4; i++)
        #pragma unroll
        for (int j = 0; j < 4; j++)
            #pragma unroll
            for (int q = 0; q < 4; q++) acc[i][j][q] = 0.f;

    auto load_stage = [&](int kt, int s) {
        const float* ag = A + (size_t)arow * Kdim + kt * 32 + acol;
        uint32_t ad = su + (uint32_t)(s * (A_ST + B_ST) + arow * 36 + acol) * 4;
        #pragma unroll
        for (int i = 0; i < 4; i++)
            CPASYNC16(ad + i * 16, ag + i * 4);
        const float* bg = B + (size_t)(kt * 32 + brow) * Ndim + bseg;
        uint32_t bd = su + (uint32_t)(s * (A_ST + B_ST) + A_ST + brow * 136 + bseg) * 4;
        #pragma unroll
        for (int i = 0; i < 4; i++)
            CPASYNC16(bd + i * 128, bg + i * 32);
        CPCOMMIT();
    };

    const int KT = Kdim >> 5;   // 32 or 128
    load_stage(0, 0);
    load_stage(1, 1);

    int s = 0;          // stage holding kt
    int sw = 2;         // stage to write kt+2 into
    for (int kt = 0; kt < KT; kt++) {
        if (kt + 1 < KT) { CPWAIT(1); } else { CPWAIT(0); }
        __syncthreads();

        const uint32_t asu = su + (uint32_t)(s * (A_ST + B_ST)) * 4;
        const float* bs = sm + s * (A_ST + B_ST) + A_ST;
        const uint32_t abase = asu + (uint32_t)((wm + lrow) * 36 + lcol) * 4;

        #pragma unroll
        for (int ks = 0; ks < 4; ks++) {
            const int k0 = ks * 8;
            uint32_t afr[4][4], bfr[4][2];
            #pragma unroll
            for (int i = 0; i < 4; i++)
                ldsm_x4(afr[i], abase + (uint32_t)(i * 16 * 36 + k0) * 4);
            #pragma unroll
            for (int j = 0; j < 4; j++) {
                const float* bp = bs + (k0 + tg) * 136 + wn + j * 8 + g;
                bfr[j][0] = __float_as_uint(bp[0]);        // raw f32: HW truncates to tf32
                bfr[j][1] = __float_as_uint(bp[4 * 136]);
            }
            #pragma unroll
            for (int i = 0; i < 4; i++)
                #pragma unroll
                for (int j = 0; j < 4; j++)
                    mma_tf32(acc[i][j], afr[i], bfr[j]);
        }

        if (kt + 2 < KT) load_stage(kt + 2, sw);
        if (++s == NSTAGE) s = 0;
        if (++sw == NSTAGE) sw = 0;
    }

    // epilogue
    #pragma unroll
    for (int j = 0; j < 4; j++) {
        const int col = wn + j * 8 + 2 * tg;
        float2 bv = *reinterpret_cast<const float2*>(bias + col);
        #pragma unroll
        for (int i = 0; i < 4; i++) {
            const int r0 = wm + i * 16 + g;
            float v00 = acc[i][j][0] + bv.x, v01 = acc[i][j][1] + bv.y;
            float v10 = acc[i][j][2] + bv.x, v11 = acc[i][j][3] + bv.y;
            if (RELU) {
                v00 = fmaxf(v00, 0.f); v01 = fmaxf(v01, 0.f);
                v10 = fmaxf(v10, 0.f); v11 = fmaxf(v11, 0.f);
            }
            if (CVT) {
                v00 = tf32r(v00); v01 = tf32r(v01);
                v10 = tf32r(v10); v11 = tf32r(v11);
            }
            *reinterpret_cast<float2*>(C + (size_t)r0 * Ndim + col) = make_float2(v00, v01);
            *reinterpret_cast<float2*>(C + (size_t)(r0 + 8) * Ndim + col) = make_float2(v10, v11);
        }
    }
}

// ---------------- K6: gather ----------------
__global__ void gather_kernel(float* __restrict__ out)
{
    int t = blockIdx.x;
    int s = g_slot[t];
    float4* dst = reinterpret_cast<float4*>(out + (size_t)t * MDIM);
    if (s < 0) {
        dst[threadIdx.x] = make_float4(0.f, 0.f, 0.f, 0.f);
        return;
    }
    float g = g_gate[t];
    float4 v = reinterpret_cast<const float4*>(g_oute + (size_t)s * MDIM)[threadIdx.x];
    dst[threadIdx.x] = make_float4(v.x * g, v.y * g, v.z * g, v.w * g);
}

// ---------------- launch ----------------
extern "C" void kernel_launch(void* const* d_in, const int* in_sizes, int n_in,
                              void* d_out, int out_size)
{
    const float* x  = (const float*)d_in[0];
    const float* wg = (const float*)d_in[1];
    const float* w1 = (const float*)d_in[2];
    const float* b1 = (const float*)d_in[3];
    const float* w2 = (const float*)d_in[4];
    const float* b2 = (const float*)d_in[5];
    float* out = (float*)d_out;

    float *disp, *h, *oute;
    cudaGetSymbolAddress((void**)&disp, g_disp);
    cudaGetSymbolAddress((void**)&h,    g_h);
    cudaGetSymbolAddress((void**)&oute, g_oute);

    cudaFuncSetAttribute(moe_gemm<true, true>,
                         cudaFuncAttributeMaxDynamicSharedMemorySize, GEMM_SMEM);
    cudaFuncSetAttribute(moe_gemm<false, false>,
                         cudaFuncAttributeMaxDynamicSharedMemorySize, GEMM_SMEM);

    gate_kernel<<<T_TOK / 8, 256>>>(x, wg);
    pos_kernel<<<1, 1024>>>();
    scatter_kernel<<<T_TOK, 256>>>(x);

    moe_gemm<true, true><<<dim3(DFFD / 128, CAP / 128, NEXP), 256, GEMM_SMEM>>>(
        disp, w1, b1, h, DFFD, MDIM);

    moe_gemm<false, false><<<dim3(MDIM / 128, CAP / 128, NEXP), 256, GEMM_SMEM>>>(
        h, w2, b2, oute, MDIM, DFFD);

    gather_kernel<<<T_TOK, 256>>>(out);
}